// round 3
// baseline (speedup 1.0000x reference)
#include <cuda_runtime.h>

#define FULL_MASK 0xFFFFFFFFu
static constexpr int HID = 32;
static constexpr int TT = 1024;
static constexpr int CELLS_PER_WARP = 2;

// ---- packed f32x2 helpers (sm_103a; ptxas never auto-fuses these) ----
__device__ __forceinline__ unsigned long long pack2(float lo, float hi) {
    unsigned long long r;
    asm("mov.b64 %0, {%1, %2};" : "=l"(r) : "f"(lo), "f"(hi));
    return r;
}
__device__ __forceinline__ void unpack2(unsigned long long v, float& lo, float& hi) {
    asm("mov.b64 {%0, %1}, %2;" : "=f"(lo), "=f"(hi) : "l"(v));
}
__device__ __forceinline__ unsigned long long fma2(unsigned long long a,
                                                   unsigned long long b,
                                                   unsigned long long c) {
    unsigned long long d;
    asm("fma.rn.f32x2 %0, %1, %2, %3;" : "=l"(d) : "l"(a), "l"(b), "l"(c));
    return d;
}
__device__ __forceinline__ float ex2f(float x) {
    float r; asm("ex2.approx.f32 %0, %1;" : "=f"(r) : "f"(x)); return r;
}
__device__ __forceinline__ float rcpf(float x) {
    float r; asm("rcp.approx.f32 %0, %1;" : "=f"(r) : "f"(x)); return r;
}
// sigmoid(x) = 1 / (1 + 2^(-x*log2(e)))  — ex2/rcp approx are ~2^-22 rel err
__device__ __forceinline__ float fast_sigmoid(float x) {
    return rcpf(1.0f + ex2f(-1.4426950408889634f * x));
}
// tanh(x) = 2*sigmoid(2x) - 1
__device__ __forceinline__ float fast_tanh(float x) {
    float r = rcpf(1.0f + ex2f(-2.8853900817779268f * x));
    return fmaf(2.0f, r, -1.0f);
}

// One warp per CTA (32 threads), TWO independent cells (batch elements) per
// warp sharing the register-resident W_hh (128 regs). lane j owns hidden
// unit j of both cells. 4 independent fma2 chains per step keep the fma pipe
// busy inside a single warp; skeleton ops (shfl/STS/syncwarp/LDS/loop) are
// amortized over 2 cells.
__global__ void __launch_bounds__(32)
lstm_kernel(const float* __restrict__ x,
            const float* __restrict__ W_ih,
            const float* __restrict__ W_hh,
            const float* __restrict__ b_ih,
            const float* __restrict__ b_hh,
            const float* __restrict__ fc_W,
            const float* __restrict__ fc_b,
            float* __restrict__ out, int B)
{
    __shared__ __align__(16) float2 hbuf[CELLS_PER_WARP][2][HID];
    const int lane = threadIdx.x & 31;
    const int b0 = blockIdx.x * CELLS_PER_WARP;
    const int b1 = min(b0 + 1, B - 1);   // clamp (B is even in practice)

    // Gate order (PyTorch): rows [0:32)=i, [32:64)=f, [64:96)=g, [96:128)=o
    unsigned long long Wif[HID], Wgo[HID];
    #pragma unroll
    for (int k = 0; k < HID; ++k) {
        Wif[k] = pack2(W_hh[(0 * HID + lane) * HID + k],
                       W_hh[(1 * HID + lane) * HID + k]);
        Wgo[k] = pack2(W_hh[(2 * HID + lane) * HID + k],
                       W_hh[(3 * HID + lane) * HID + k]);
    }
    const unsigned long long wih_if = pack2(W_ih[0 * HID + lane], W_ih[1 * HID + lane]);
    const unsigned long long wih_go = pack2(W_ih[2 * HID + lane], W_ih[3 * HID + lane]);
    const unsigned long long bias_if =
        pack2(b_ih[0 * HID + lane] + b_hh[0 * HID + lane],
              b_ih[1 * HID + lane] + b_hh[1 * HID + lane]);
    const unsigned long long bias_go =
        pack2(b_ih[2 * HID + lane] + b_hh[2 * HID + lane],
              b_ih[3 * HID + lane] + b_hh[3 * HID + lane]);

    float hA = 0.0f, cA = 0.0f, hB = 0.0f, cB = 0.0f;
    const float* xrowA = x + (size_t)b0 * TT;
    const float* xrowB = x + (size_t)b1 * TT;

    for (int t0 = 0; t0 < TT; t0 += 32) {
        // one coalesced 128B read per cell per 32 steps
        const float xbufA = xrowA[t0 + lane];
        const float xbufB = xrowB[t0 + lane];
        #pragma unroll 2
        for (int s = 0; s < 32; ++s) {
            const float xvA = __shfl_sync(FULL_MASK, xbufA, s);
            const float xvB = __shfl_sync(FULL_MASK, xbufB, s);
            unsigned long long aif = fma2(pack2(xvA, xvA), wih_if, bias_if);
            unsigned long long ago = fma2(pack2(xvA, xvA), wih_go, bias_go);
            unsigned long long bif = fma2(pack2(xvB, xvB), wih_if, bias_if);
            unsigned long long bgo = fma2(pack2(xvB, xvB), wih_go, bias_go);

            // broadcast both cells' h through ping-pong buffers, one sync
            float2* bufA = hbuf[0][s & 1];
            float2* bufB = hbuf[1][s & 1];
            bufA[lane] = make_float2(hA, hA);
            bufB[lane] = make_float2(hB, hB);
            __syncwarp();
            const ulonglong2* pA = reinterpret_cast<const ulonglong2*>(bufA);
            const ulonglong2* pB = reinterpret_cast<const ulonglong2*>(bufB);
            #pragma unroll
            for (int k2 = 0; k2 < HID / 2; ++k2) {
                const ulonglong2 ha = pA[k2];   // LDS.128 broadcast, N=1
                const ulonglong2 hb = pB[k2];
                aif = fma2(Wif[2 * k2],     ha.x, aif);
                ago = fma2(Wgo[2 * k2],     ha.x, ago);
                bif = fma2(Wif[2 * k2],     hb.x, bif);
                bgo = fma2(Wgo[2 * k2],     hb.x, bgo);
                aif = fma2(Wif[2 * k2 + 1], ha.y, aif);
                ago = fma2(Wgo[2 * k2 + 1], ha.y, ago);
                bif = fma2(Wif[2 * k2 + 1], hb.y, bif);
                bgo = fma2(Wgo[2 * k2 + 1], hb.y, bgo);
            }

            float ai, af, ag, ao;
            unpack2(aif, ai, af);
            unpack2(ago, ag, ao);
            float bi, bf, bg, bo;
            unpack2(bif, bi, bf);
            unpack2(bgo, bg, bo);

            const float igA = fast_sigmoid(ai);
            const float fgA = fast_sigmoid(af);
            const float ggA = fast_tanh(ag);
            const float ogA = fast_sigmoid(ao);
            const float igB = fast_sigmoid(bi);
            const float fgB = fast_sigmoid(bf);
            const float ggB = fast_tanh(bg);
            const float ogB = fast_sigmoid(bo);

            cA = fmaf(fgA, cA, igA * ggA);
            cB = fmaf(fgB, cB, igB * ggB);
            hA = ogA * fast_tanh(cA);
            hB = ogB * fast_tanh(cB);
        }
    }

    // out[b] = h . fc_W + fc_b  (warp reduce, both cells)
    const float w = fc_W[lane];
    float vA = hA * w;
    float vB = hB * w;
    #pragma unroll
    for (int off = 16; off; off >>= 1) {
        vA += __shfl_xor_sync(FULL_MASK, vA, off);
        vB += __shfl_xor_sync(FULL_MASK, vB, off);
    }
    if (lane == 0) {
        out[b0] = vA + fc_b[0];
        if (b1 != b0) out[b1] = vB + fc_b[0];
    }
}

extern "C" void kernel_launch(void* const* d_in, const int* in_sizes, int n_in,
                              void* d_out, int out_size) {
    const float* x    = (const float*)d_in[0];
    const float* W_ih = (const float*)d_in[1];
    const float* W_hh = (const float*)d_in[2];
    const float* b_ih = (const float*)d_in[3];
    const float* b_hh = (const float*)d_in[4];
    const float* fc_W = (const float*)d_in[5];
    const float* fc_b = (const float*)d_in[6];
    float* out = (float*)d_out;

    const int B = in_sizes[0] / TT;           // x is B*T*1 elements
    const int ctas = (B + CELLS_PER_WARP - 1) / CELLS_PER_WARP;
    lstm_kernel<<<ctas, 32>>>(x, W_ih, W_hh, b_ih, b_hh, fc_W, fc_b, out, B);
}